// round 9
// baseline (speedup 1.0000x reference)
#include <cuda_runtime.h>

// Fixed problem structure (M=512 checks, N=1024 vars, SHIFTS=(0,7,101)):
//   E = 3072 edges, check degree 6, var degree 3.
//   edges sorted by (check,var) => check c owns edges [6c, 6c+6).
#define ITERS 5
#define MCHK  512
#define NVAR  1024
#define NEDGE 3072

#define LOG2E 1.4426950408889634f
#define LN2   0.6931471805599453f

typedef unsigned long long u64;

// ---- Blackwell packed f32x2 helpers (PTX-only; ptxas never auto-fuses) ----
__device__ __forceinline__ u64 f2pk(float lo, float hi) {
    u64 r; asm("mov.b64 %0, {%1, %2};" : "=l"(r) : "f"(lo), "f"(hi)); return r;
}
__device__ __forceinline__ void f2up(float& lo, float& hi, u64 v) {
    asm("mov.b64 {%0, %1}, %2;" : "=f"(lo), "=f"(hi) : "l"(v));
}
__device__ __forceinline__ u64 add2(u64 a, u64 b) {
    u64 r; asm("add.rn.f32x2 %0, %1, %2;" : "=l"(r) : "l"(a), "l"(b)); return r;
}
__device__ __forceinline__ u64 mul2(u64 a, u64 b) {
    u64 r; asm("mul.rn.f32x2 %0, %1, %2;" : "=l"(r) : "l"(a), "l"(b)); return r;
}
__device__ __forceinline__ u64 fma2(u64 a, u64 b, u64 c) {
    u64 r; asm("fma.rn.f32x2 %0, %1, %2, %3;" : "=l"(r) : "l"(a), "l"(b), "l"(c)); return r;
}
__device__ __forceinline__ float frcp(float x) {
    float r; asm("rcp.approx.f32 %0, %1;" : "=f"(r) : "f"(x)); return r;
}

// g_fast: 1 iff w_iter==1 && llr_iter==1 everywhere (verified by prepack,
// which only ever writes 0 -> monotone, race-free, deterministic per input).
__device__ int    g_fast = 1;
__device__ float4 g_wlt [ITERS * NEDGE];  // general path: {w0, w1, llr_iter*log2e, 0}
__device__ int2   g_sib [NEDGE];          // {sib0_bytes | sib1_bytes<<16, ev}
__device__ float2 g_fw  [NEDGE];          // {bitcast(fidx), w_final*ln2}

__global__ void prepack_kernel(const float* __restrict__ w_iter,
                               const float* __restrict__ llr_iter,
                               const int*   __restrict__ vs_idx,
                               const int*   __restrict__ edge_var,
                               const int*   __restrict__ fin_idx,
                               const float* __restrict__ w_final)
{
    const int c = threadIdx.x;
    const int t = blockIdx.x;
    bool ok = true;
#pragma unroll
    for (int j = 0; j < 6; ++j) {
        const int e  = 6 * c + j;
        const float w0 = w_iter[t * 2 * NEDGE + 2 * e];
        const float w1 = w_iter[t * 2 * NEDGE + 2 * e + 1];
        const float li = llr_iter[t * NVAR + edge_var[e]];
        ok = ok && (w0 == 1.0f) && (w1 == 1.0f) && (li == 1.0f);
        g_wlt[t * NEDGE + j * MCHK + c] = make_float4(w0, w1, li * LOG2E, 0.0f);
    }
    if (!ok) g_fast = 0;
    if (t == 0) {
#pragma unroll
        for (int j = 0; j < 6; ++j) {
            const int e  = 6 * c + j;
            const int s0 = vs_idx[2 * e];
            const int s1 = vs_idx[2 * e + 1];
            const int b0 = ((s0 % 6) * MCHK + s0 / 6) * 4;   // byte offsets < 2^14
            const int b1 = ((s1 % 6) * MCHK + s1 / 6) * 4;
            g_sib[j * MCHK + c] = make_int2(b0 | (b1 << 16), edge_var[e]);
        }
#pragma unroll
        for (int k = 0; k < 2; ++k)
#pragma unroll
            for (int p = 0; p < 3; ++p) {
                const int v = c + MCHK * k;
                const int q = 3 * v + p;
                const int e = fin_idx[q];
                float2 fw;
                fw.x = __int_as_float((e % 6) * MCHK + e / 6);
                fw.y = w_final[q] * LN2;
                g_fw[(k * 3 + p) * MCHK + c] = fw;
            }
    }
}

// Exclusive products (pair-tree, depth 3), 0.9995 damping folded in:
// m[j] = 0.9995 * prod_{k != j} v[k]
__device__ __forceinline__ void excl_prod(const float v[6], float m[6])
{
    const float p01  = v[0] * v[1];
    const float p23  = v[2] * v[3];
    const float p45s = (0.9995f * v[4]) * v[5];
    const float B = p23 * p45s;            // excl {0,1}, scaled
    const float C = p01 * p45s;            // excl {2,3}, scaled
    const float D = 0.9995f * (p01 * p23); // excl {4,5}, scaled
    m[0] = v[1] * B;  m[1] = v[0] * B;
    m[2] = v[3] * C;  m[3] = v[2] * C;
    m[4] = v[5] * D;  m[5] = v[4] * D;
}

// General-path check update in log2 domain.
__device__ __forceinline__ void check_update_log(const float x_in[6], float c2v[6])
{
    float n[6], d[6];
#pragma unroll
    for (int j = 0; j < 6; ++j) {
        const float x  = fminf(fmaxf(x_in[j], -25.0f), 25.0f);
        const float ea = exp2f(x);
        n[j] = ea - 1.0f;
        d[j] = ea + 1.0f;
    }
    float sn[6], sd[6];
    sn[5] = 1.0f; sd[5] = 1.0f;
#pragma unroll
    for (int j = 4; j >= 0; --j) {
        sn[j] = sn[j + 1] * n[j + 1];
        sd[j] = sd[j + 1] * d[j + 1];
    }
    float pn = 0.9995f, pd = 1.0f;
#pragma unroll
    for (int j = 0; j < 6; ++j) {
        const float P = pn * sn[j];
        const float Q = pd * sd[j];
        c2v[j] = __log2f(Q + P) - __log2f(Q - P);
        pn *= n[j];
        pd *= d[j];
    }
}

__global__ __launch_bounds__(512, 3)
void bp_decode_kernel(const float* __restrict__ llr,        // [B, N]
                      const float* __restrict__ llr_final,  // [N]
                      float*       __restrict__ out)        // [B, N]
{
    __shared__ float sm[2][NEDGE];      // double-buffered messages

    const int b = blockIdx.x;
    const int c = threadIdx.x;
    const float* __restrict__ llr_b = llr + (size_t)b * NVAR;

    unsigned int sibpk[6];              // packed {sb0 | sb1<<16}
    float pl[6];                        // pl = tanh(llr/2) of this edge's variable
#pragma unroll
    for (int j = 0; j < 6; ++j) {
        const int2 s = g_sib[j * MCHK + c];          // 1 LDG.64 per j
        sibpk[j] = (unsigned int)s.x;
        const float lvj = __ldg(&llr_b[s.y]);
        const float e = __expf(lvj);
        pl[j] = 1.0f - __fdividef(2.0f, e + 1.0f);   // NaN-safe at +-inf
    }

    int cur = 0;
    if (g_fast) {
        // ======= fast path: unit weights -> tanh-domain loop, no logs =======
        // message m = tanh(c2v/2) = 0.9995 * prod v2c (check node's native output)
        // variable update: v2c = combine(combine(m_a,m_b), pl), combine=(x+y)/(1+xy)
        // Inner combine executed as packed f32x2 (2 edges per instruction).
        const u64 ONE2 = f2pk(1.0f, 1.0f);
        u64 PL2[3];
#pragma unroll
        for (int p = 0; p < 3; ++p) PL2[p] = f2pk(pl[2 * p], pl[2 * p + 1]);

        float m[6];
        excl_prod(pl, m);                            // peeled iteration 0

#pragma unroll
        for (int t = 1; t < ITERS; ++t) {
            const char* smc = (const char*)sm[cur];
#pragma unroll
            for (int j = 0; j < 6; ++j) sm[cur][j * MCHK + c] = m[j];
            __syncthreads();

            float v2c[6];
#pragma unroll
            for (int p = 0; p < 3; ++p) {
                const unsigned int k0 = sibpk[2 * p], k1 = sibpk[2 * p + 1];
                const float ma0 = *(const float*)(smc + (k0 & 0xFFFFu));
                const float mb0 = *(const float*)(smc + (k0 >> 16));
                const float ma1 = *(const float*)(smc + (k1 & 0xFFFFu));
                const float mb1 = *(const float*)(smc + (k1 >> 16));
                const u64 MA  = f2pk(ma0, ma1);
                const u64 MB  = f2pk(mb0, mb1);
                const u64 S   = add2(MA, MB);            // ma+mb
                const u64 D1  = fma2(MA, MB, ONE2);      // 1+ma*mb
                const u64 NUM = fma2(PL2[p], D1, S);     // pl*(1+mamb)+(ma+mb)
                const u64 DEN = fma2(PL2[p], S, D1);     // pl*(ma+mb)+(1+mamb) > 0
                float d0, d1;
                f2up(d0, d1, DEN);
                const u64 R = f2pk(frcp(d0), frcp(d1));  // 2 scalar MUFU.RCP
                const u64 V = mul2(NUM, R);
                f2up(v2c[2 * p], v2c[2 * p + 1], V);
            }
            excl_prod(v2c, m);
            cur ^= 1;
        }

        // epilogue: publish tanh-domain messages, convert with atanh once
#pragma unroll
        for (int j = 0; j < 6; ++j) sm[cur][j * MCHK + c] = m[j];
        __syncthreads();

        float* __restrict__ out_b = out + (size_t)b * NVAR;
#pragma unroll
        for (int k = 0; k < 2; ++k) {
            const int v = c + MCHK * k;
            float marg = 0.0f;
#pragma unroll
            for (int p = 0; p < 3; ++p) {
                const float2 fw = g_fw[(k * 3 + p) * MCHK + c];
                const float  mm = sm[cur][__float_as_int(fw.x)];
                // c2v/ln2 = log2(1+mm) - log2(1-mm); fw.y prescaled by ln2
                marg += fw.y * (__log2f(1.0f + mm) - __log2f(1.0f - mm));
            }
            marg += __ldg(&llr_b[v]) * llr_final[v];
            out_b[v] = __fdividef(1.0f, 1.0f + __expf(-marg));
        }
    } else {
        // ======= general path: arbitrary weights, log2-domain messages =======
        float lv[6];
#pragma unroll
        for (int j = 0; j < 6; ++j) lv[j] = __ldg(&llr_b[g_sib[j * MCHK + c].y]);

        float c2v[6], x[6];
        {
            const float4* __restrict__ wlt = g_wlt;  // t=0, messages zero
#pragma unroll
            for (int j = 0; j < 6; ++j) x[j] = lv[j] * wlt[j * MCHK + c].z;
            check_update_log(x, c2v);
        }
#pragma unroll
        for (int t = 1; t < ITERS; ++t) {
            const float4* __restrict__ wlt = g_wlt + t * NEDGE;
            const char* smc = (const char*)sm[cur];
#pragma unroll
            for (int j = 0; j < 6; ++j) sm[cur][j * MCHK + c] = c2v[j];
            __syncthreads();
#pragma unroll
            for (int j = 0; j < 6; ++j) {
                const float4 w  = wlt[j * MCHK + c];
                const float  m0 = *(const float*)(smc + (sibpk[j] & 0xFFFFu));
                const float  m1 = *(const float*)(smc + (sibpk[j] >> 16));
                x[j] = m0 * w.x + m1 * w.y + lv[j] * w.z;
            }
            check_update_log(x, c2v);
            cur ^= 1;
        }

#pragma unroll
        for (int j = 0; j < 6; ++j) sm[cur][j * MCHK + c] = c2v[j];
        __syncthreads();

        float* __restrict__ out_b = out + (size_t)b * NVAR;
#pragma unroll
        for (int k = 0; k < 2; ++k) {
            const int v = c + MCHK * k;
            float marg = 0.0f;
#pragma unroll
            for (int p = 0; p < 3; ++p) {
                const float2 fw = g_fw[(k * 3 + p) * MCHK + c];
                marg += sm[cur][__float_as_int(fw.x)] * fw.y;
            }
            marg += __ldg(&llr_b[v]) * llr_final[v];
            out_b[v] = __fdividef(1.0f, 1.0f + __expf(-marg));
        }
    }
}

extern "C" void kernel_launch(void* const* d_in, const int* in_sizes, int n_in,
                              void* d_out, int out_size)
{
    // metadata order: llr, w_iter, llr_iter, w_final, llr_final,
    //                 v_sum_idx, seg_vsum, c_prod_idx, seg_cprod,
    //                 final_idx, seg_final, edge_var
    const float* llr       = (const float*)d_in[0];
    const float* w_iter    = (const float*)d_in[1];
    const float* llr_iter  = (const float*)d_in[2];
    const float* w_final   = (const float*)d_in[3];
    const float* llr_final = (const float*)d_in[4];
    const int*   vs_idx    = (const int*)  d_in[5];
    const int*   fin_idx   = (const int*)  d_in[9];
    const int*   edge_var  = (const int*)  d_in[11];
    float*       out       = (float*)d_out;

    const int B = in_sizes[0] / NVAR;

    prepack_kernel<<<ITERS, MCHK>>>(w_iter, llr_iter, vs_idx, edge_var,
                                    fin_idx, w_final);
    bp_decode_kernel<<<B, MCHK>>>(llr, llr_final, out);
}

// round 10
// speedup vs baseline: 1.1066x; 1.1066x over previous
#include <cuda_runtime.h>

// Fixed problem structure (M=512 checks, N=1024 vars, SHIFTS=(0,7,101)):
//   E = 3072 edges, check degree 6, var degree 3.
//   edges sorted by (check,var) => check c owns edges [6c, 6c+6).
#define ITERS 5
#define MCHK  512
#define NVAR  1024
#define NEDGE 3072

#define LOG2E 1.4426950408889634f
#define LN2   0.6931471805599453f

// g_fast: 1 iff w_iter==1 && llr_iter==1 && w_final==1 && llr_final==1
// everywhere (verified by prepack, which only ever writes 0 -> monotone,
// race-free, deterministic per input).
__device__ int    g_fast = 1;
__device__ float4 g_wlt [ITERS * NEDGE];  // general path: {w0, w1, llr_iter*log2e, 0}
__device__ int2   g_sib [NEDGE];          // {sib0_bytes | sib1_bytes<<16, ev}
__device__ float2 g_fw  [NEDGE];          // {bitcast(fidx), w_final*ln2}

__global__ void prepack_kernel(const float* __restrict__ w_iter,
                               const float* __restrict__ llr_iter,
                               const int*   __restrict__ vs_idx,
                               const int*   __restrict__ edge_var,
                               const int*   __restrict__ fin_idx,
                               const float* __restrict__ w_final,
                               const float* __restrict__ llr_final)
{
    const int c = threadIdx.x;
    const int t = blockIdx.x;
    bool ok = true;
#pragma unroll
    for (int j = 0; j < 6; ++j) {
        const int e  = 6 * c + j;
        const float w0 = w_iter[t * 2 * NEDGE + 2 * e];
        const float w1 = w_iter[t * 2 * NEDGE + 2 * e + 1];
        const float li = llr_iter[t * NVAR + edge_var[e]];
        ok = ok && (w0 == 1.0f) && (w1 == 1.0f) && (li == 1.0f);
        g_wlt[t * NEDGE + j * MCHK + c] = make_float4(w0, w1, li * LOG2E, 0.0f);
    }
    if (t == 0) {
#pragma unroll
        for (int j = 0; j < 6; ++j) {
            const int e  = 6 * c + j;
            const int s0 = vs_idx[2 * e];
            const int s1 = vs_idx[2 * e + 1];
            const int b0 = ((s0 % 6) * MCHK + s0 / 6) * 4;   // byte offsets < 2^14
            const int b1 = ((s1 % 6) * MCHK + s1 / 6) * 4;
            g_sib[j * MCHK + c] = make_int2(b0 | (b1 << 16), edge_var[e]);
        }
#pragma unroll
        for (int k = 0; k < 2; ++k) {
            const int v = c + MCHK * k;
            ok = ok && (llr_final[v] == 1.0f);
#pragma unroll
            for (int p = 0; p < 3; ++p) {
                const int q = 3 * v + p;
                const int e = fin_idx[q];
                const float wf = w_final[q];
                ok = ok && (wf == 1.0f);
                float2 fw;
                fw.x = __int_as_float((e % 6) * MCHK + e / 6);
                fw.y = wf * LN2;
                g_fw[(k * 3 + p) * MCHK + c] = fw;
            }
        }
    }
    if (!ok) g_fast = 0;
}

// Exclusive products (pair-tree, depth 3), 0.9995 damping folded in:
// m[j] = 0.9995 * prod_{k != j} v[k]
__device__ __forceinline__ void excl_prod(const float v[6], float m[6])
{
    const float p01  = v[0] * v[1];
    const float p23  = v[2] * v[3];
    const float p45s = (0.9995f * v[4]) * v[5];
    const float B = p23 * p45s;            // excl {0,1}, scaled
    const float C = p01 * p45s;            // excl {2,3}, scaled
    const float D = 0.9995f * (p01 * p23); // excl {4,5}, scaled
    m[0] = v[1] * B;  m[1] = v[0] * B;
    m[2] = v[3] * C;  m[3] = v[2] * C;
    m[4] = v[5] * D;  m[5] = v[4] * D;
}

// General-path check update in log2 domain.
__device__ __forceinline__ void check_update_log(const float x_in[6], float c2v[6])
{
    float n[6], d[6];
#pragma unroll
    for (int j = 0; j < 6; ++j) {
        const float x  = fminf(fmaxf(x_in[j], -25.0f), 25.0f);
        const float ea = exp2f(x);
        n[j] = ea - 1.0f;
        d[j] = ea + 1.0f;
    }
    float sn[6], sd[6];
    sn[5] = 1.0f; sd[5] = 1.0f;
#pragma unroll
    for (int j = 4; j >= 0; --j) {
        sn[j] = sn[j + 1] * n[j + 1];
        sd[j] = sd[j + 1] * d[j + 1];
    }
    float pn = 0.9995f, pd = 1.0f;
#pragma unroll
    for (int j = 0; j < 6; ++j) {
        const float P = pn * sn[j];
        const float Q = pd * sd[j];
        c2v[j] = __log2f(Q + P) - __log2f(Q - P);
        pn *= n[j];
        pd *= d[j];
    }
}

__global__ __launch_bounds__(512, 3)
void bp_decode_kernel(const float* __restrict__ llr,        // [B, N]
                      const float* __restrict__ llr_final,  // [N]
                      float*       __restrict__ out)        // [B, N]
{
    __shared__ float sm[2][NEDGE];      // double-buffered messages

    const int b = blockIdx.x;
    const int c = threadIdx.x;
    const float* __restrict__ llr_b = llr + (size_t)b * NVAR;

    unsigned int sibpk[6];              // packed {sb0 | sb1<<16}
    float pl[6];                        // pl = tanh(llr/2) of this edge's variable
#pragma unroll
    for (int j = 0; j < 6; ++j) {
        const int2 s = g_sib[j * MCHK + c];          // 1 LDG.64 per j
        sibpk[j] = (unsigned int)s.x;
        const float lvj = __ldg(&llr_b[s.y]);
        const float e = __expf(lvj);
        pl[j] = 1.0f - __fdividef(2.0f, e + 1.0f);   // NaN-safe at +-inf
    }

    int cur = 0;
    if (g_fast) {
        // ======= fast path: unit weights -> tanh-domain loop, no logs =======
        // message m = tanh(c2v/2) = 0.9995 * prod v2c (check node's native output)
        // variable update: v2c = combine(combine(m_a,m_b), pl), combine=(x+y)/(1+xy)
        float m[6];
        excl_prod(pl, m);                            // peeled iteration 0

#pragma unroll
        for (int t = 1; t < ITERS; ++t) {
            const char* smc = (const char*)sm[cur];
#pragma unroll
            for (int j = 0; j < 6; ++j) sm[cur][j * MCHK + c] = m[j];
            __syncthreads();

            float v2c[6];
#pragma unroll
            for (int j = 0; j < 6; ++j) {
                const float ma = *(const float*)(smc + (sibpk[j] & 0xFFFFu));
                const float mb = *(const float*)(smc + (sibpk[j] >> 16));
                const float num1 = ma + mb;
                const float den1 = fmaf(ma, mb, 1.0f);
                const float num  = fmaf(pl[j], den1, num1);
                const float den  = fmaf(pl[j], num1, den1); // > 0 (|m|<=0.9995)
                v2c[j] = __fdividef(num, den);
            }
            excl_prod(v2c, m);
            cur ^= 1;
        }

        // log-free epilogue (valid because w_final==1 && llr_final==1):
        //   sigmoid(sum_p 2*atanh(m_p) + llr)
        //     = 1 / (1 + e^{-llr} * prod_p (1-m_p)/(1+m_p))
#pragma unroll
        for (int j = 0; j < 6; ++j) sm[cur][j * MCHK + c] = m[j];
        __syncthreads();

        float* __restrict__ out_b = out + (size_t)b * NVAR;
#pragma unroll
        for (int k = 0; k < 2; ++k) {
            const int v = c + MCHK * k;
            float mp[3];
#pragma unroll
            for (int p = 0; p < 3; ++p) {
                const float2 fw = g_fw[(k * 3 + p) * MCHK + c];
                mp[p] = sm[cur][__float_as_int(fw.x)];
            }
            const float numr = (1.0f - mp[0]) * (1.0f - mp[1]) * (1.0f - mp[2]);
            const float denr = (1.0f + mp[0]) * (1.0f + mp[1]) * (1.0f + mp[2]);
            const float enl  = __expf(-__ldg(&llr_b[v]));      // e^{-llr}
            const float tq   = enl * __fdividef(numr, denr);   // >= 0
            out_b[v] = __fdividef(1.0f, 1.0f + tq);
        }
    } else {
        // ======= general path: arbitrary weights, log2-domain messages =======
        float lv[6];
#pragma unroll
        for (int j = 0; j < 6; ++j) lv[j] = __ldg(&llr_b[g_sib[j * MCHK + c].y]);

        float c2v[6], x[6];
        {
            const float4* __restrict__ wlt = g_wlt;  // t=0, messages zero
#pragma unroll
            for (int j = 0; j < 6; ++j) x[j] = lv[j] * wlt[j * MCHK + c].z;
            check_update_log(x, c2v);
        }
#pragma unroll
        for (int t = 1; t < ITERS; ++t) {
            const float4* __restrict__ wlt = g_wlt + t * NEDGE;
            const char* smc = (const char*)sm[cur];
#pragma unroll
            for (int j = 0; j < 6; ++j) sm[cur][j * MCHK + c] = c2v[j];
            __syncthreads();
#pragma unroll
            for (int j = 0; j < 6; ++j) {
                const float4 w  = wlt[j * MCHK + c];
                const float  m0 = *(const float*)(smc + (sibpk[j] & 0xFFFFu));
                const float  m1 = *(const float*)(smc + (sibpk[j] >> 16));
                x[j] = m0 * w.x + m1 * w.y + lv[j] * w.z;
            }
            check_update_log(x, c2v);
            cur ^= 1;
        }

#pragma unroll
        for (int j = 0; j < 6; ++j) sm[cur][j * MCHK + c] = c2v[j];
        __syncthreads();

        float* __restrict__ out_b = out + (size_t)b * NVAR;
#pragma unroll
        for (int k = 0; k < 2; ++k) {
            const int v = c + MCHK * k;
            float marg = 0.0f;
#pragma unroll
            for (int p = 0; p < 3; ++p) {
                const float2 fw = g_fw[(k * 3 + p) * MCHK + c];
                marg += sm[cur][__float_as_int(fw.x)] * fw.y;  // fw.y prescaled *ln2
            }
            marg += __ldg(&llr_b[v]) * llr_final[v];
            out_b[v] = __fdividef(1.0f, 1.0f + __expf(-marg));
        }
    }
}

extern "C" void kernel_launch(void* const* d_in, const int* in_sizes, int n_in,
                              void* d_out, int out_size)
{
    // metadata order: llr, w_iter, llr_iter, w_final, llr_final,
    //                 v_sum_idx, seg_vsum, c_prod_idx, seg_cprod,
    //                 final_idx, seg_final, edge_var
    const float* llr       = (const float*)d_in[0];
    const float* w_iter    = (const float*)d_in[1];
    const float* llr_iter  = (const float*)d_in[2];
    const float* w_final   = (const float*)d_in[3];
    const float* llr_final = (const float*)d_in[4];
    const int*   vs_idx    = (const int*)  d_in[5];
    const int*   fin_idx   = (const int*)  d_in[9];
    const int*   edge_var  = (const int*)  d_in[11];
    float*       out       = (float*)d_out;

    const int B = in_sizes[0] / NVAR;

    prepack_kernel<<<ITERS, MCHK>>>(w_iter, llr_iter, vs_idx, edge_var,
                                    fin_idx, w_final, llr_final);
    bp_decode_kernel<<<B, MCHK>>>(llr, llr_final, out);
}

// round 11
// speedup vs baseline: 1.1541x; 1.0429x over previous
#include <cuda_runtime.h>

// Fixed problem structure (M=512 checks, N=1024 vars, SHIFTS=(0,7,101)):
//   E = 3072 edges, check degree 6, var degree 3.
//   edges sorted by (check,var) => check c owns edges [6c, 6c+6).
#define ITERS 5
#define MCHK  512
#define NVAR  1024
#define NEDGE 3072

#define LOG2E 1.4426950408889634f
#define LN2   0.6931471805599453f

// g_fast: 1 iff w_iter==1 && llr_iter==1 && w_final==1 && llr_final==1
// everywhere (verified by prepack, which only ever writes 0 -> monotone,
// race-free, deterministic per input).
__device__ int    g_fast = 1;
__device__ float4 g_wlt [ITERS * NEDGE];  // general path: {w0, w1, llr_iter*log2e, 0}
__device__ int2   g_sib [NEDGE];          // {sib0_bytes | sib1_bytes<<16, ev}
__device__ float2 g_fw  [NEDGE];          // {bitcast(fidx), w_final*ln2}

__global__ void prepack_kernel(const float* __restrict__ w_iter,
                               const float* __restrict__ llr_iter,
                               const int*   __restrict__ vs_idx,
                               const int*   __restrict__ edge_var,
                               const int*   __restrict__ fin_idx,
                               const float* __restrict__ w_final,
                               const float* __restrict__ llr_final)
{
    const int c = threadIdx.x;
    const int t = blockIdx.x;
    bool ok = true;
#pragma unroll
    for (int j = 0; j < 6; ++j) {
        const int e  = 6 * c + j;
        const float w0 = w_iter[t * 2 * NEDGE + 2 * e];
        const float w1 = w_iter[t * 2 * NEDGE + 2 * e + 1];
        const float li = llr_iter[t * NVAR + edge_var[e]];
        ok = ok && (w0 == 1.0f) && (w1 == 1.0f) && (li == 1.0f);
        g_wlt[t * NEDGE + j * MCHK + c] = make_float4(w0, w1, li * LOG2E, 0.0f);
    }
    if (t == 0) {
#pragma unroll
        for (int j = 0; j < 6; ++j) {
            const int e  = 6 * c + j;
            const int s0 = vs_idx[2 * e];
            const int s1 = vs_idx[2 * e + 1];
            const int b0 = ((s0 % 6) * MCHK + s0 / 6) * 4;   // byte offsets < 2^14
            const int b1 = ((s1 % 6) * MCHK + s1 / 6) * 4;
            g_sib[j * MCHK + c] = make_int2(b0 | (b1 << 16), edge_var[e]);
        }
#pragma unroll
        for (int k = 0; k < 2; ++k) {
            const int v = c + MCHK * k;
            ok = ok && (llr_final[v] == 1.0f);
#pragma unroll
            for (int p = 0; p < 3; ++p) {
                const int q = 3 * v + p;
                const int e = fin_idx[q];
                const float wf = w_final[q];
                ok = ok && (wf == 1.0f);
                float2 fw;
                fw.x = __int_as_float((e % 6) * MCHK + e / 6);
                fw.y = wf * LN2;
                g_fw[(k * 3 + p) * MCHK + c] = fw;
            }
        }
    }
    if (!ok) g_fast = 0;
}

// Exclusive products (pair-tree, depth 3), 0.9995 damping folded in:
// m[j] = 0.9995 * prod_{k != j} v[k]
__device__ __forceinline__ void excl_prod(const float v[6], float m[6])
{
    const float p01  = v[0] * v[1];
    const float p23  = v[2] * v[3];
    const float p45s = (0.9995f * v[4]) * v[5];
    const float B = p23 * p45s;            // excl {0,1}, scaled
    const float C = p01 * p45s;            // excl {2,3}, scaled
    const float D = 0.9995f * (p01 * p23); // excl {4,5}, scaled
    m[0] = v[1] * B;  m[1] = v[0] * B;
    m[2] = v[3] * C;  m[3] = v[2] * C;
    m[4] = v[5] * D;  m[5] = v[4] * D;
}

// General-path check update in log2 domain.
__device__ __forceinline__ void check_update_log(const float x_in[6], float c2v[6])
{
    float n[6], d[6];
#pragma unroll
    for (int j = 0; j < 6; ++j) {
        const float x  = fminf(fmaxf(x_in[j], -25.0f), 25.0f);
        const float ea = exp2f(x);
        n[j] = ea - 1.0f;
        d[j] = ea + 1.0f;
    }
    float sn[6], sd[6];
    sn[5] = 1.0f; sd[5] = 1.0f;
#pragma unroll
    for (int j = 4; j >= 0; --j) {
        sn[j] = sn[j + 1] * n[j + 1];
        sd[j] = sd[j + 1] * d[j + 1];
    }
    float pn = 0.9995f, pd = 1.0f;
#pragma unroll
    for (int j = 0; j < 6; ++j) {
        const float P = pn * sn[j];
        const float Q = pd * sd[j];
        c2v[j] = __log2f(Q + P) - __log2f(Q - P);
        pn *= n[j];
        pd *= d[j];
    }
}

__global__ __launch_bounds__(512, 4)
void bp_decode_kernel(const float* __restrict__ llr,        // [B, N]
                      const float* __restrict__ llr_final,  // [N]
                      float*       __restrict__ out)        // [B, N]
{
    __shared__ float sm[2][NEDGE];      // double-buffered messages (24.6 KB)

    const int b = blockIdx.x;
    const int c = threadIdx.x;
    const float* __restrict__ llr_b = llr + (size_t)b * NVAR;

    unsigned int sibpk[6];              // packed {sb0 | sb1<<16}
    float pl[6];                        // pl = tanh(llr/2) of this edge's variable
#pragma unroll
    for (int j = 0; j < 6; ++j) {
        const int2 s = g_sib[j * MCHK + c];          // 1 LDG.64 per j
        sibpk[j] = (unsigned int)s.x;
        const float lvj = __ldg(&llr_b[s.y]);
        const float e = __expf(lvj);
        pl[j] = 1.0f - __fdividef(2.0f, e + 1.0f);   // NaN-safe at +-inf
    }

    int cur = 0;
    if (g_fast) {
        // ======= fast path: unit weights -> tanh-domain loop, no logs =======
        // message m = tanh(c2v/2) = 0.9995 * prod v2c (check node's native output)
        // variable update: v2c = combine(combine(m_a,m_b), pl), combine=(x+y)/(1+xy)
        float m[6];
        excl_prod(pl, m);                            // peeled iteration 0

#pragma unroll
        for (int t = 1; t < ITERS; ++t) {
            const char* smc = (const char*)sm[cur];
#pragma unroll
            for (int j = 0; j < 6; ++j) sm[cur][j * MCHK + c] = m[j];
            __syncthreads();

            float v2c[6];
#pragma unroll
            for (int j = 0; j < 6; ++j) {
                const float ma = *(const float*)(smc + (sibpk[j] & 0xFFFFu));
                const float mb = *(const float*)(smc + (sibpk[j] >> 16));
                const float num1 = ma + mb;
                const float den1 = fmaf(ma, mb, 1.0f);
                const float num  = fmaf(pl[j], den1, num1);
                const float den  = fmaf(pl[j], num1, den1); // > 0 (|m|<=0.9995)
                v2c[j] = __fdividef(num, den);
            }
            excl_prod(v2c, m);
            cur ^= 1;
        }

        // log-free epilogue (valid because w_final==1 && llr_final==1):
        //   sigmoid(sum_p 2*atanh(m_p) + llr)
        //     = 1 / (1 + e^{-llr} * prod_p (1-m_p)/(1+m_p))
#pragma unroll
        for (int j = 0; j < 6; ++j) sm[cur][j * MCHK + c] = m[j];
        __syncthreads();

        float* __restrict__ out_b = out + (size_t)b * NVAR;
#pragma unroll
        for (int k = 0; k < 2; ++k) {
            const int v = c + MCHK * k;
            float mp[3];
#pragma unroll
            for (int p = 0; p < 3; ++p) {
                const float2 fw = g_fw[(k * 3 + p) * MCHK + c];
                mp[p] = sm[cur][__float_as_int(fw.x)];
            }
            const float numr = (1.0f - mp[0]) * (1.0f - mp[1]) * (1.0f - mp[2]);
            const float denr = (1.0f + mp[0]) * (1.0f + mp[1]) * (1.0f + mp[2]);
            const float enl  = __expf(-__ldg(&llr_b[v]));      // e^{-llr}
            const float tq   = enl * __fdividef(numr, denr);   // >= 0
            out_b[v] = __fdividef(1.0f, 1.0f + tq);
        }
    } else {
        // ======= general path: arbitrary weights, log2-domain messages =======
        // (may spill at the 32-reg cap; correctness preserved, and this path is
        //  only taken for non-unit weight inputs)
        float lv[6];
#pragma unroll
        for (int j = 0; j < 6; ++j) lv[j] = __ldg(&llr_b[g_sib[j * MCHK + c].y]);

        float c2v[6], x[6];
        {
            const float4* __restrict__ wlt = g_wlt;  // t=0, messages zero
#pragma unroll
            for (int j = 0; j < 6; ++j) x[j] = lv[j] * wlt[j * MCHK + c].z;
            check_update_log(x, c2v);
        }
#pragma unroll
        for (int t = 1; t < ITERS; ++t) {
            const float4* __restrict__ wlt = g_wlt + t * NEDGE;
            const char* smc = (const char*)sm[cur];
#pragma unroll
            for (int j = 0; j < 6; ++j) sm[cur][j * MCHK + c] = c2v[j];
            __syncthreads();
#pragma unroll
            for (int j = 0; j < 6; ++j) {
                const float4 w  = wlt[j * MCHK + c];
                const float  m0 = *(const float*)(smc + (sibpk[j] & 0xFFFFu));
                const float  m1 = *(const float*)(smc + (sibpk[j] >> 16));
                x[j] = m0 * w.x + m1 * w.y + lv[j] * w.z;
            }
            check_update_log(x, c2v);
            cur ^= 1;
        }

#pragma unroll
        for (int j = 0; j < 6; ++j) sm[cur][j * MCHK + c] = c2v[j];
        __syncthreads();

        float* __restrict__ out_b = out + (size_t)b * NVAR;
#pragma unroll
        for (int k = 0; k < 2; ++k) {
            const int v = c + MCHK * k;
            float marg = 0.0f;
#pragma unroll
            for (int p = 0; p < 3; ++p) {
                const float2 fw = g_fw[(k * 3 + p) * MCHK + c];
                marg += sm[cur][__float_as_int(fw.x)] * fw.y;  // fw.y prescaled *ln2
            }
            marg += __ldg(&llr_b[v]) * llr_final[v];
            out_b[v] = __fdividef(1.0f, 1.0f + __expf(-marg));
        }
    }
}

extern "C" void kernel_launch(void* const* d_in, const int* in_sizes, int n_in,
                              void* d_out, int out_size)
{
    // metadata order: llr, w_iter, llr_iter, w_final, llr_final,
    //                 v_sum_idx, seg_vsum, c_prod_idx, seg_cprod,
    //                 final_idx, seg_final, edge_var
    const float* llr       = (const float*)d_in[0];
    const float* w_iter    = (const float*)d_in[1];
    const float* llr_iter  = (const float*)d_in[2];
    const float* w_final   = (const float*)d_in[3];
    const float* llr_final = (const float*)d_in[4];
    const int*   vs_idx    = (const int*)  d_in[5];
    const int*   fin_idx   = (const int*)  d_in[9];
    const int*   edge_var  = (const int*)  d_in[11];
    float*       out       = (float*)d_out;

    const int B = in_sizes[0] / NVAR;

    prepack_kernel<<<ITERS, MCHK>>>(w_iter, llr_iter, vs_idx, edge_var,
                                    fin_idx, w_final, llr_final);
    bp_decode_kernel<<<B, MCHK>>>(llr, llr_final, out);
}